// round 1
// baseline (speedup 1.0000x reference)
#include <cuda_runtime.h>
#include <math.h>

#define T_TOK 4096
#define H_DIM 1024
#define I_DIM 4096
#define NE 8
#define TOPK 2
#define ROWS_TOT (T_TOK * TOPK)

#define BM 64
#define BN 64
#define BK 16

// ---------------- scratch (static device globals; no runtime alloc) ----------------
__device__ int   g_cnt[NE];
__device__ int   g_off[NE];
__device__ int   g_tok[NE * T_TOK];            // token id per (expert, local row)
__device__ int   g_sel_e[T_TOK * TOPK];
__device__ int   g_sel_r[T_TOK * TOPK];
__device__ float g_sel_w[T_TOK * TOPK];
__device__ float g_act[ROWS_TOT * I_DIM];      // 128 MB: silu(g)*u per (row, I)
__device__ float g_down[ROWS_TOT * H_DIM];     // 32 MB: down-proj per row (unweighted)

// ---------------- reset ----------------
__global__ void reset_kernel() {
    if (threadIdx.x < NE) g_cnt[threadIdx.x] = 0;
}

// ---------------- router: logits, softmax, top-2, routing lists ----------------
__global__ void router_kernel(const float* __restrict__ x,
                              const float* __restrict__ rw,
                              float* __restrict__ out, int extras) {
    int t = blockIdx.x;
    int tid = threadIdx.x;           // 256 threads: warp e computes logit e
    int e = tid >> 5, lane = tid & 31;
    const float* xt = x + (size_t)t * H_DIM;
    float s = 0.f;
    for (int h = lane; h < H_DIM; h += 32) s += xt[h] * rw[h * NE + e];
    #pragma unroll
    for (int o = 16; o > 0; o >>= 1) s += __shfl_xor_sync(0xffffffffu, s, o);
    __shared__ float lg[NE];
    if (lane == 0) lg[e] = s;
    __syncthreads();
    if (tid == 0) {
        float mx = lg[0];
        #pragma unroll
        for (int i = 1; i < NE; i++) mx = fmaxf(mx, lg[i]);
        float p[NE]; float den = 0.f;
        #pragma unroll
        for (int i = 0; i < NE; i++) { p[i] = expf(lg[i] - mx); den += p[i]; }
        // top-2, ties -> lowest index (matches jax.lax.top_k)
        int e0 = 0;
        #pragma unroll
        for (int i = 1; i < NE; i++) if (p[i] > p[e0]) e0 = i;
        int e1 = (e0 == 0) ? 1 : 0;
        #pragma unroll
        for (int i = 0; i < NE; i++) if (i != e0 && p[i] > p[e1]) e1 = i;
        float p0 = p[e0], p1 = p[e1];
        float inv = 1.f / (p0 + p1);
        float w0 = p0 * inv, w1 = p1 * inv;
        int r0 = atomicAdd(&g_cnt[e0], 1);
        int r1 = atomicAdd(&g_cnt[e1], 1);
        g_tok[e0 * T_TOK + r0] = t;
        g_tok[e1 * T_TOK + r1] = t;
        g_sel_e[2 * t] = e0;     g_sel_r[2 * t] = r0;     g_sel_w[2 * t] = w0;
        g_sel_e[2 * t + 1] = e1; g_sel_r[2 * t + 1] = r1; g_sel_w[2 * t + 1] = w1;
        if (extras) {
            float* lo = out + (size_t)T_TOK * H_DIM;
            #pragma unroll
            for (int i = 0; i < NE; i++) lo[(size_t)t * NE + i] = lg[i];
            float* se = out + (size_t)T_TOK * H_DIM + (size_t)T_TOK * NE;
            se[2 * t] = (float)e0;
            se[2 * t + 1] = (float)e1;
        }
    }
}

// ---------------- exclusive scan of expert counts (E=8, trivial) ----------------
__global__ void scan_kernel() {
    int o = 0;
    for (int e = 0; e < NE; e++) { g_off[e] = o; o += g_cnt[e]; }
}

// ---------------- phase A: act = silu(X_e @ Wg_e) * (X_e @ Wu_e), gathered rows ----
__global__ __launch_bounds__(128, 4)
void gateup_kernel(const float* __restrict__ x,
                   const float* __restrict__ wg,
                   const float* __restrict__ wu) {
    int e = blockIdx.z;
    int cnt = g_cnt[e];
    int m0 = blockIdx.y * BM;
    if (m0 >= cnt) return;
    int n0 = blockIdx.x * BN;
    int off = g_off[e];

    __shared__ float sA[BK][BM];
    __shared__ float sBg[BK][BN];
    __shared__ float sBu[BK][BN];

    int tid = threadIdx.x;
    int tx = tid & 15;    // 16 cols of 4
    int ty = tid >> 4;    // 8 rows of 8

    float accg[8][4], accu[8][4];
    #pragma unroll
    for (int r = 0; r < 8; r++)
        #pragma unroll
        for (int c = 0; c < 4; c++) { accg[r][c] = 0.f; accu[r][c] = 0.f; }

    const float* wge = wg + (size_t)e * H_DIM * I_DIM;
    const float* wue = wu + (size_t)e * H_DIM * I_DIM;

    int am = tid >> 1;
    int ak = (tid & 1) * 8;
    const float* xrow = 0;
    { int mr = m0 + am; if (mr < cnt) xrow = x + (size_t)g_tok[e * T_TOK + mr] * H_DIM; }

    int bk = tid >> 3;        // 0..15
    int bn = (tid & 7) * 8;   // 0..56

    for (int k0 = 0; k0 < H_DIM; k0 += BK) {
        float av[8];
        if (xrow) {
            float4 a0 = *(const float4*)(xrow + k0 + ak);
            float4 a1 = *(const float4*)(xrow + k0 + ak + 4);
            av[0]=a0.x; av[1]=a0.y; av[2]=a0.z; av[3]=a0.w;
            av[4]=a1.x; av[5]=a1.y; av[6]=a1.z; av[7]=a1.w;
        } else {
            #pragma unroll
            for (int j = 0; j < 8; j++) av[j] = 0.f;
        }
        const float* bgp = wge + (size_t)(k0 + bk) * I_DIM + n0 + bn;
        const float* bup = wue + (size_t)(k0 + bk) * I_DIM + n0 + bn;
        float4 bg0 = *(const float4*)bgp;
        float4 bg1 = *(const float4*)(bgp + 4);
        float4 bu0 = *(const float4*)bup;
        float4 bu1 = *(const float4*)(bup + 4);

        #pragma unroll
        for (int j = 0; j < 8; j++) sA[ak + j][am] = av[j];
        *(float4*)&sBg[bk][bn]     = bg0;
        *(float4*)&sBg[bk][bn + 4] = bg1;
        *(float4*)&sBu[bk][bn]     = bu0;
        *(float4*)&sBu[bk][bn + 4] = bu1;
        __syncthreads();

        #pragma unroll
        for (int kk = 0; kk < BK; kk++) {
            float a[8];
            float4 t0 = *(const float4*)&sA[kk][ty * 8];
            float4 t1 = *(const float4*)&sA[kk][ty * 8 + 4];
            a[0]=t0.x; a[1]=t0.y; a[2]=t0.z; a[3]=t0.w;
            a[4]=t1.x; a[5]=t1.y; a[6]=t1.z; a[7]=t1.w;
            float4 bgv = *(const float4*)&sBg[kk][tx * 4];
            float4 buv = *(const float4*)&sBu[kk][tx * 4];
            float bga[4] = {bgv.x, bgv.y, bgv.z, bgv.w};
            float bua[4] = {buv.x, buv.y, buv.z, buv.w};
            #pragma unroll
            for (int r = 0; r < 8; r++)
                #pragma unroll
                for (int c = 0; c < 4; c++) {
                    accg[r][c] += a[r] * bga[c];
                    accu[r][c] += a[r] * bua[c];
                }
        }
        __syncthreads();
    }

    #pragma unroll
    for (int r = 0; r < 8; r++) {
        int gm = m0 + ty * 8 + r;
        if (gm < cnt) {
            float* dst = g_act + (size_t)(off + gm) * I_DIM + n0 + tx * 4;
            float4 o;
            float g0 = accg[r][0]; o.x = (g0 / (1.f + expf(-g0))) * accu[r][0];
            float g1 = accg[r][1]; o.y = (g1 / (1.f + expf(-g1))) * accu[r][1];
            float g2 = accg[r][2]; o.z = (g2 / (1.f + expf(-g2))) * accu[r][2];
            float g3 = accg[r][3]; o.w = (g3 / (1.f + expf(-g3))) * accu[r][3];
            *(float4*)dst = o;
        }
    }
}

// ---------------- phase B: down = act_e @ Wd_e ----------------
__global__ __launch_bounds__(128, 4)
void down_kernel(const float* __restrict__ wd) {
    int e = blockIdx.z;
    int cnt = g_cnt[e];
    int m0 = blockIdx.y * BM;
    if (m0 >= cnt) return;
    int n0 = blockIdx.x * BN;
    int off = g_off[e];

    __shared__ float sA[BK][BM];
    __shared__ float sB[BK][BN];

    int tid = threadIdx.x;
    int tx = tid & 15;
    int ty = tid >> 4;

    float acc[8][4];
    #pragma unroll
    for (int r = 0; r < 8; r++)
        #pragma unroll
        for (int c = 0; c < 4; c++) acc[r][c] = 0.f;

    const float* wde = wd + (size_t)e * I_DIM * H_DIM;

    int am = tid >> 1;
    int ak = (tid & 1) * 8;
    const float* arow = 0;
    { int mr = m0 + am; if (mr < cnt) arow = g_act + (size_t)(off + mr) * I_DIM; }

    int bk = tid >> 3;
    int bn = (tid & 7) * 8;

    for (int k0 = 0; k0 < I_DIM; k0 += BK) {
        float av[8];
        if (arow) {
            float4 a0 = *(const float4*)(arow + k0 + ak);
            float4 a1 = *(const float4*)(arow + k0 + ak + 4);
            av[0]=a0.x; av[1]=a0.y; av[2]=a0.z; av[3]=a0.w;
            av[4]=a1.x; av[5]=a1.y; av[6]=a1.z; av[7]=a1.w;
        } else {
            #pragma unroll
            for (int j = 0; j < 8; j++) av[j] = 0.f;
        }
        const float* bp = wde + (size_t)(k0 + bk) * H_DIM + n0 + bn;
        float4 b0 = *(const float4*)bp;
        float4 b1 = *(const float4*)(bp + 4);

        #pragma unroll
        for (int j = 0; j < 8; j++) sA[ak + j][am] = av[j];
        *(float4*)&sB[bk][bn]     = b0;
        *(float4*)&sB[bk][bn + 4] = b1;
        __syncthreads();

        #pragma unroll
        for (int kk = 0; kk < BK; kk++) {
            float a[8];
            float4 t0 = *(const float4*)&sA[kk][ty * 8];
            float4 t1 = *(const float4*)&sA[kk][ty * 8 + 4];
            a[0]=t0.x; a[1]=t0.y; a[2]=t0.z; a[3]=t0.w;
            a[4]=t1.x; a[5]=t1.y; a[6]=t1.z; a[7]=t1.w;
            float4 bv = *(const float4*)&sB[kk][tx * 4];
            float ba[4] = {bv.x, bv.y, bv.z, bv.w};
            #pragma unroll
            for (int r = 0; r < 8; r++)
                #pragma unroll
                for (int c = 0; c < 4; c++) acc[r][c] += a[r] * ba[c];
        }
        __syncthreads();
    }

    #pragma unroll
    for (int r = 0; r < 8; r++) {
        int gm = m0 + ty * 8 + r;
        if (gm < cnt) {
            float* dst = g_down + (size_t)(off + gm) * H_DIM + n0 + tx * 4;
            float4 o; o.x = acc[r][0]; o.y = acc[r][1]; o.z = acc[r][2]; o.w = acc[r][3];
            *(float4*)dst = o;
        }
    }
}

// ---------------- combine: out[t] = w0*down[slot0] + w1*down[slot1] (deterministic) ----
__global__ void combine_kernel(float* __restrict__ out) {
    int t = blockIdx.x;
    __shared__ int s0s, s1s;
    __shared__ float w0s, w1s;
    if (threadIdx.x == 0) {
        int e0 = g_sel_e[2 * t], e1 = g_sel_e[2 * t + 1];
        s0s = g_off[e0] + g_sel_r[2 * t];
        s1s = g_off[e1] + g_sel_r[2 * t + 1];
        w0s = g_sel_w[2 * t];
        w1s = g_sel_w[2 * t + 1];
    }
    __syncthreads();
    const float* d0 = g_down + (size_t)s0s * H_DIM;
    const float* d1 = g_down + (size_t)s1s * H_DIM;
    float* o = out + (size_t)t * H_DIM;
    float w0 = w0s, w1 = w1s;
    for (int h = threadIdx.x; h < H_DIM; h += blockDim.x)
        o[h] = w0 * d0[h] + w1 * d1[h];
}

// ---------------- launch ----------------
extern "C" void kernel_launch(void* const* d_in, const int* in_sizes, int n_in,
                              void* d_out, int out_size) {
    const float* x  = (const float*)d_in[0];   // hidden_states [4,1024,1024]
    const float* rw = (const float*)d_in[1];   // router_w [1024,8]
    const float* wg = (const float*)d_in[2];   // w_gate [8,1024,4096]
    const float* wu = (const float*)d_in[3];   // w_up   [8,1024,4096]
    const float* wd = (const float*)d_in[4];   // w_down [8,4096,1024]
    float* out = (float*)d_out;

    int extras = (out_size >= T_TOK * H_DIM + T_TOK * NE + T_TOK * TOPK) ? 1 : 0;

    reset_kernel<<<1, 32>>>();
    router_kernel<<<T_TOK, 256>>>(x, rw, out, extras);
    scan_kernel<<<1, 1>>>();

    dim3 ga(I_DIM / BN, T_TOK / BM, NE);   // (64, 64, 8); tiles past cnt[e] exit early
    gateup_kernel<<<ga, 128>>>(x, wg, wu);

    dim3 gb(H_DIM / BN, T_TOK / BM, NE);   // (16, 64, 8)
    down_kernel<<<gb, 128>>>(wd);

    combine_kernel<<<T_TOK, 256>>>(out);
}